// round 1
// baseline (speedup 1.0000x reference)
#include <cuda_runtime.h>
#include <cstdint>

#define NROWS 8192
#define D_IN  64
#define D_OUT 32000
#define BM 64
#define BN 128
#define NBLK (D_OUT / BN)   // 250 column blocks

// Scratch (no allocations allowed): per-(row, colblock) partial exp-sums and per-row 1/sum.
__device__ float g_partials[NROWS * NBLK];   // 8.2 MB
__device__ float g_rowinv[NROWS];

// ---------------------------------------------------------------------------
// Kernel 1: tiled GEMM  E = exp((1/x) @ W), written to out; per-(row,block)
// partial sums of exp into g_partials. BM=64 x BN=128, K=64 (full), 256 thr,
// 4x8 register micro-tile. Static smem = 16KB + 32KB = 48KB exactly.
// ---------------------------------------------------------------------------
__global__ __launch_bounds__(256) void gemm_exp_kernel(const float* __restrict__ x,
                                                       const float* __restrict__ w,
                                                       float* __restrict__ out) {
    __shared__ float As[D_IN][BM];   // [k][m], holds 1/x transposed
    __shared__ float Bs[D_IN][BN];   // [k][n]

    const int tid = threadIdx.x;
    const int m0 = blockIdx.y * BM;
    const int n0 = blockIdx.x * BN;

    // Load A tile (64 rows x 64 k), transpose into As with reciprocal.
    // 1024 float4 total -> 4 per thread.
#pragma unroll
    for (int i = 0; i < 4; ++i) {
        int idx = tid + i * 256;
        int row = idx >> 4;       // 0..63
        int k4  = idx & 15;       // 0..15
        float4 v = *reinterpret_cast<const float4*>(&x[(m0 + row) * D_IN + k4 * 4]);
        As[k4 * 4 + 0][row] = 1.0f / v.x;
        As[k4 * 4 + 1][row] = 1.0f / v.y;
        As[k4 * 4 + 2][row] = 1.0f / v.z;
        As[k4 * 4 + 3][row] = 1.0f / v.w;
    }
    // Load B tile (64 k x 128 n), coalesced float4. 2048 float4 -> 8 per thread.
#pragma unroll
    for (int i = 0; i < 8; ++i) {
        int idx = tid + i * 256;
        int k  = idx >> 5;        // 0..63
        int c4 = idx & 31;        // 0..31
        *reinterpret_cast<float4*>(&Bs[k][c4 * 4]) =
            *reinterpret_cast<const float4*>(&w[k * D_OUT + n0 + c4 * 4]);
    }
    __syncthreads();

    const int tx = tid & 15;      // column group: cols tx*8 .. tx*8+7
    const int ty = tid >> 4;      // row group:   rows ty*4 .. ty*4+3

    float acc[4][8];
#pragma unroll
    for (int r = 0; r < 4; ++r)
#pragma unroll
        for (int c = 0; c < 8; ++c) acc[r][c] = 0.0f;

#pragma unroll
    for (int k = 0; k < D_IN; ++k) {
        float4 a  = *reinterpret_cast<const float4*>(&As[k][ty * 4]);
        float4 b0 = *reinterpret_cast<const float4*>(&Bs[k][tx * 8]);
        float4 b1 = *reinterpret_cast<const float4*>(&Bs[k][tx * 8 + 4]);
        float av[4] = {a.x, a.y, a.z, a.w};
        float bv[8] = {b0.x, b0.y, b0.z, b0.w, b1.x, b1.y, b1.z, b1.w};
#pragma unroll
        for (int r = 0; r < 4; ++r)
#pragma unroll
            for (int c = 0; c < 8; ++c)
                acc[r][c] = fmaf(av[r], bv[c], acc[r][c]);
    }

    // Epilogue: exp (no max-subtraction needed, |logit| <= 6.4), write E,
    // reduce row partial sums across the 16 tx lanes (contiguous half-warp).
#pragma unroll
    for (int r = 0; r < 4; ++r) {
        int row = m0 + ty * 4 + r;
        float e[8];
        float s = 0.0f;
#pragma unroll
        for (int c = 0; c < 8; ++c) {
            e[c] = __expf(acc[r][c]);
            s += e[c];
        }
        float* orow = &out[(size_t)row * D_OUT + n0 + tx * 8];
        *reinterpret_cast<float4*>(orow)     = make_float4(e[0], e[1], e[2], e[3]);
        *reinterpret_cast<float4*>(orow + 4) = make_float4(e[4], e[5], e[6], e[7]);
#pragma unroll
        for (int off = 8; off >= 1; off >>= 1)
            s += __shfl_xor_sync(0xffffffffu, s, off);
        if (tx == 0) g_partials[row * NBLK + blockIdx.x] = s;
    }
}

// ---------------------------------------------------------------------------
// Kernel 2: per-row reduce of 250 partials -> 1/rowsum. One warp per row.
// ---------------------------------------------------------------------------
__global__ __launch_bounds__(256) void rowinv_kernel() {
    int warp = threadIdx.x >> 5;
    int lane = threadIdx.x & 31;
    int row  = blockIdx.x * 8 + warp;
    float s = 0.0f;
    for (int i = lane; i < NBLK; i += 32) s += g_partials[row * NBLK + i];
#pragma unroll
    for (int off = 16; off >= 1; off >>= 1)
        s += __shfl_xor_sync(0xffffffffu, s, off);
    if (lane == 0) g_rowinv[row] = 1.0f / s;
}

// ---------------------------------------------------------------------------
// Kernel 3: rescale E in place by 1/rowsum. float4 vectorized.
// ---------------------------------------------------------------------------
__global__ __launch_bounds__(256) void scale_kernel(float* __restrict__ out) {
    int row = blockIdx.y;
    int j = (blockIdx.x * 256 + threadIdx.x) * 4;
    if (j >= D_OUT) return;
    float inv = g_rowinv[row];
    float4* p = reinterpret_cast<float4*>(&out[(size_t)row * D_OUT + j]);
    float4 v = *p;
    v.x *= inv; v.y *= inv; v.z *= inv; v.w *= inv;
    *p = v;
}

// ---------------------------------------------------------------------------
// Kernel 4: zero any tail elements (aux_loss scalar == 0 exactly).
// ---------------------------------------------------------------------------
__global__ void tail_kernel(float* __restrict__ out, long long base, long long n) {
    long long i = (long long)blockIdx.x * 256 + threadIdx.x;
    if (i < n) out[base + i] = 0.0f;
}

extern "C" void kernel_launch(void* const* d_in, const int* in_sizes, int n_in,
                              void* d_out, int out_size) {
    const float* x = (const float*)d_in[0];              // (8192, 64)
    const float* w = (const float*)d_in[1];              // (64, 32000)
    float* out = (float*)d_out;

    dim3 ggrid(NBLK, NROWS / BM);                        // (250, 128)
    gemm_exp_kernel<<<ggrid, 256>>>(x, w, out);

    rowinv_kernel<<<NROWS / 8, 256>>>();

    dim3 sgrid((D_OUT / 4 + 255) / 256, NROWS);          // (32, 8192)
    scale_kernel<<<sgrid, 256>>>(out);

    long long n_main = (long long)NROWS * D_OUT;
    long long tail = (long long)out_size - n_main;
    if (tail > 0) {
        int blocks = (int)((tail + 255) / 256);
        tail_kernel<<<blocks, 256>>>(out, n_main, tail);
    }
}

// round 3
// speedup vs baseline: 1.6768x; 1.6768x over previous
#include <cuda_runtime.h>
#include <cuda_bf16.h>
#include <cstdint>

#define NROWS 8192
#define D_IN  64
#define D_OUT 32000
#define MT 128
#define NT 128
#define NBLK   (D_OUT / NT)     // 250 column blocks
#define NBLK2  (NBLK * 2)       // 500: one partial per (row, warp-n-half)
#define MBLK   (NROWS / MT)     // 64

// smem row pitch: 72 bf16 = 144 B = 36 words -> 8 consecutive rows hit
// disjoint bank groups (4*r + w covers 32 banks), conflict-free LDS.
#define PITCH_W 36

// -------------------- device scratch (no allocs allowed) --------------------
__device__ uint32_t g_wt_hi[D_OUT * 32];   // W^T rows: [n][32] u32 = 64 bf16
__device__ uint32_t g_wt_lo[D_OUT * 32];
__device__ float    g_partials[NROWS * NBLK2];  // 16.4 MB
__device__ float    g_rowinv[NROWS];

__device__ __forceinline__ uint32_t pack_bf2(float a, float b) {
    uint32_t lo = __bfloat16_as_ushort(__float2bfloat16_rn(a));
    uint32_t hi = __bfloat16_as_ushort(__float2bfloat16_rn(b));
    return lo | (hi << 16);
}

__device__ __forceinline__ void mma_bf16(float* c, const uint32_t* a, uint32_t b0, uint32_t b1) {
    asm volatile(
        "mma.sync.aligned.m16n8k16.row.col.f32.bf16.bf16.f32 "
        "{%0,%1,%2,%3}, {%4,%5,%6,%7}, {%8,%9}, {%0,%1,%2,%3};"
        : "+f"(c[0]), "+f"(c[1]), "+f"(c[2]), "+f"(c[3])
        : "r"(a[0]), "r"(a[1]), "r"(a[2]), "r"(a[3]), "r"(b0), "r"(b1));
}

// ---------------------------------------------------------------------------
// prep_w: W[64][32000] -> transposed bf16 hi/lo rows [32000][64] (128B each)
// ---------------------------------------------------------------------------
__global__ __launch_bounds__(256) void prep_w_kernel(const float* __restrict__ w) {
    int n = blockIdx.x * 256 + threadIdx.x;
    uint32_t hi[32], lo[32];
#pragma unroll
    for (int j = 0; j < 32; ++j) {
        float v0 = w[(2 * j) * D_OUT + n];
        float v1 = w[(2 * j + 1) * D_OUT + n];
        __nv_bfloat16 h0 = __float2bfloat16_rn(v0);
        __nv_bfloat16 h1 = __float2bfloat16_rn(v1);
        hi[j] = (uint32_t)__bfloat16_as_ushort(h0) | ((uint32_t)__bfloat16_as_ushort(h1) << 16);
        lo[j] = pack_bf2(v0 - __bfloat162float(h0), v1 - __bfloat162float(h1));
    }
    uint4* dh = reinterpret_cast<uint4*>(g_wt_hi) + (size_t)n * 8;
    uint4* dl = reinterpret_cast<uint4*>(g_wt_lo) + (size_t)n * 8;
#pragma unroll
    for (int j = 0; j < 8; ++j) {
        dh[j] = make_uint4(hi[4*j], hi[4*j+1], hi[4*j+2], hi[4*j+3]);
        dl[j] = make_uint4(lo[4*j], lo[4*j+1], lo[4*j+2], lo[4*j+3]);
    }
}

// ---------------------------------------------------------------------------
// Main HMMA pass. do_store=0: accumulate exp-sums into g_partials.
//                 do_store=1: out[row][col] = exp(logit) * g_rowinv[row].
// Grid (NBLK, MBLK), 256 threads, dynamic smem 72KB.
// ---------------------------------------------------------------------------
__global__ __launch_bounds__(256)
void mma_pass_kernel(const float* __restrict__ x, float* __restrict__ out, int do_store) {
    extern __shared__ uint32_t smem[];
    uint32_t* sAhi = smem;                       // [128][36] words
    uint32_t* sAlo = smem + 128 * PITCH_W;
    uint32_t* sBhi = smem + 2 * 128 * PITCH_W;   // W^T: [n][36] words
    uint32_t* sBlo = smem + 3 * 128 * PITCH_W;

    const int tid  = threadIdx.x;
    const int wid  = tid >> 5;
    const int lane = tid & 31;
    const int m0 = blockIdx.y * MT;
    const int n0 = blockIdx.x * NT;

    // ---- load A: 1/x -> bf16 hi/lo. 256 thr: row=tid>>1, half=tid&1 ----
    {
        int row = tid >> 1, half = tid & 1;
        const float4* xr = reinterpret_cast<const float4*>(
            &x[(size_t)(m0 + row) * D_IN + half * 32]);
        uint32_t* dh = &sAhi[row * PITCH_W + half * 16];
        uint32_t* dl = &sAlo[row * PITCH_W + half * 16];
#pragma unroll
        for (int j = 0; j < 8; ++j) {
            float4 v = xr[j];
            float r0 = 1.0f / v.x, r1 = 1.0f / v.y, r2 = 1.0f / v.z, r3 = 1.0f / v.w;
            __nv_bfloat16 h0 = __float2bfloat16_rn(r0), h1 = __float2bfloat16_rn(r1);
            __nv_bfloat16 h2 = __float2bfloat16_rn(r2), h3 = __float2bfloat16_rn(r3);
            uint32_t p0 = (uint32_t)__bfloat16_as_ushort(h0) | ((uint32_t)__bfloat16_as_ushort(h1) << 16);
            uint32_t p1 = (uint32_t)__bfloat16_as_ushort(h2) | ((uint32_t)__bfloat16_as_ushort(h3) << 16);
            dh[2*j]   = p0;
            dh[2*j+1] = p1;
            dl[2*j]   = pack_bf2(r0 - __bfloat162float(h0), r1 - __bfloat162float(h1));
            dl[2*j+1] = pack_bf2(r2 - __bfloat162float(h2), r3 - __bfloat162float(h3));
        }
    }
    // ---- load B^T rows (prepped bf16) ----
    {
        int n = tid >> 1, half = tid & 1;
        const uint4* sh = reinterpret_cast<const uint4*>(g_wt_hi + (size_t)(n0 + n) * 32 + half * 16);
        const uint4* sl = reinterpret_cast<const uint4*>(g_wt_lo + (size_t)(n0 + n) * 32 + half * 16);
        uint4* dh = reinterpret_cast<uint4*>(&sBhi[n * PITCH_W + half * 16]);
        uint4* dl = reinterpret_cast<uint4*>(&sBlo[n * PITCH_W + half * 16]);
#pragma unroll
        for (int q = 0; q < 4; ++q) { dh[q] = sh[q]; dl[q] = sl[q]; }
    }
    __syncthreads();

    // ---- mainloop: 12 HMMA-k-steps (4 kc x 3 compensation terms) ----
    const int wm = wid & 3;    // 0..3: m quarter
    const int wn = wid >> 2;   // 0..1: n half
    const int g  = lane >> 2;  // group row
    const int t  = lane & 3;   // thread-in-group

    float acc[2][8][4];
#pragma unroll
    for (int mi = 0; mi < 2; ++mi)
#pragma unroll
        for (int ni = 0; ni < 8; ++ni)
#pragma unroll
            for (int c = 0; c < 4; ++c) acc[mi][ni][c] = 0.0f;

    const int aRow = wm * 32 + g;          // row for mi=0 (a0/a2); +16 for mi=1
    const int bRow0 = wn * 64 + g;         // n for ni=0; +8 per ni

#pragma unroll
    for (int kc = 0; kc < 4; ++kc) {
        const int wb = kc * 8 + t;         // k word for a0/a1/b0; +4 for a2/a3/b1
        uint32_t ahi[2][4], alo[2][4];
#pragma unroll
        for (int mi = 0; mi < 2; ++mi) {
            int r = (aRow + mi * 16) * PITCH_W;
            ahi[mi][0] = sAhi[r + wb];
            ahi[mi][1] = sAhi[r + 8 * PITCH_W + wb];
            ahi[mi][2] = sAhi[r + wb + 4];
            ahi[mi][3] = sAhi[r + 8 * PITCH_W + wb + 4];
            alo[mi][0] = sAlo[r + wb];
            alo[mi][1] = sAlo[r + 8 * PITCH_W + wb];
            alo[mi][2] = sAlo[r + wb + 4];
            alo[mi][3] = sAlo[r + 8 * PITCH_W + wb + 4];
        }
#pragma unroll
        for (int ni = 0; ni < 8; ++ni) {
            int nb = (bRow0 + ni * 8) * PITCH_W;
            uint32_t b0h = sBhi[nb + wb], b1h = sBhi[nb + wb + 4];
            uint32_t b0l = sBlo[nb + wb], b1l = sBlo[nb + wb + 4];
#pragma unroll
            for (int mi = 0; mi < 2; ++mi) {
                mma_bf16(acc[mi][ni], ahi[mi], b0h, b1h);
                mma_bf16(acc[mi][ni], alo[mi], b0h, b1h);
                mma_bf16(acc[mi][ni], ahi[mi], b0l, b1l);
            }
        }
    }

    // ---- epilogue: exp, then either row-partial-sums or normalized store ----
#pragma unroll
    for (int mi = 0; mi < 2; ++mi) {
        const int rg = m0 + wm * 32 + mi * 16 + g;   // global row (and rg+8)
        if (do_store) {
            const float inv0 = g_rowinv[rg];
            const float inv8 = g_rowinv[rg + 8];
            float* r0p = out + (size_t)rg * D_OUT + n0 + wn * 64 + t * 2;
            float* r8p = r0p + (size_t)8 * D_OUT;
#pragma unroll
            for (int ni = 0; ni < 8; ++ni) {
                float e0 = __expf(acc[mi][ni][0]);
                float e1 = __expf(acc[mi][ni][1]);
                float e2 = __expf(acc[mi][ni][2]);
                float e3 = __expf(acc[mi][ni][3]);
                *reinterpret_cast<float2*>(r0p + ni * 8) = make_float2(e0 * inv0, e1 * inv0);
                *reinterpret_cast<float2*>(r8p + ni * 8) = make_float2(e2 * inv8, e3 * inv8);
            }
        } else {
            float s0 = 0.0f, s8 = 0.0f;
#pragma unroll
            for (int ni = 0; ni < 8; ++ni) {
                s0 += __expf(acc[mi][ni][0]) + __expf(acc[mi][ni][1]);
                s8 += __expf(acc[mi][ni][2]) + __expf(acc[mi][ni][3]);
            }
            s0 += __shfl_xor_sync(0xffffffffu, s0, 1);
            s0 += __shfl_xor_sync(0xffffffffu, s0, 2);
            s8 += __shfl_xor_sync(0xffffffffu, s8, 1);
            s8 += __shfl_xor_sync(0xffffffffu, s8, 2);
            if (t == 0) {
                int pcol = blockIdx.x * 2 + wn;
                g_partials[(size_t)rg * NBLK2 + pcol]       = s0;
                g_partials[(size_t)(rg + 8) * NBLK2 + pcol] = s8;
            }
        }
    }
}

// ---------------------------------------------------------------------------
// rowinv: reduce 500 partials per row -> 1/rowsum. One warp per row.
// ---------------------------------------------------------------------------
__global__ __launch_bounds__(256) void rowinv_kernel() {
    int warp = threadIdx.x >> 5;
    int lane = threadIdx.x & 31;
    int row = blockIdx.x * 8 + warp;
    float s = 0.0f;
    for (int i = lane; i < NBLK2; i += 32) s += g_partials[(size_t)row * NBLK2 + i];
#pragma unroll
    for (int off = 16; off >= 1; off >>= 1)
        s += __shfl_xor_sync(0xffffffffu, s, off);
    if (lane == 0) g_rowinv[row] = 1.0f / s;
}

__global__ void tail_kernel(float* __restrict__ out, long long base, long long n) {
    long long i = (long long)blockIdx.x * 256 + threadIdx.x;
    if (i < n) out[base + i] = 0.0f;
}

extern "C" void kernel_launch(void* const* d_in, const int* in_sizes, int n_in,
                              void* d_out, int out_size) {
    const float* x = (const float*)d_in[0];
    const float* w = (const float*)d_in[1];
    float* out = (float*)d_out;

    const int smem_bytes = 4 * 128 * PITCH_W * 4;   // 73728
    static int attr_set = 0;
    if (!attr_set) {
        cudaFuncSetAttribute(mma_pass_kernel,
                             cudaFuncAttributeMaxDynamicSharedMemorySize, smem_bytes);
        attr_set = 1;
    }

    prep_w_kernel<<<D_OUT / 256, 256>>>(w);

    dim3 grid(NBLK, MBLK);   // (250, 64)
    mma_pass_kernel<<<grid, 256, smem_bytes>>>(x, out, 0);  // pass 1: exp-sums
    rowinv_kernel<<<NROWS / 8, 256>>>();
    mma_pass_kernel<<<grid, 256, smem_bytes>>>(x, out, 1);  // pass 2: normalized store

    long long n_main = (long long)NROWS * D_OUT;
    long long tail = (long long)out_size - n_main;
    if (tail > 0) {
        int blocks = (int)((tail + 255) / 256);
        tail_kernel<<<blocks, 256>>>(out, n_main, tail);
    }
}